// round 1
// baseline (speedup 1.0000x reference)
#include <cuda_runtime.h>
#include <math.h>

#define TTOK 4096
#define HDIM 2048
#define IDIM 1408
#define NEXP 8
#define FINAL_ELEMS (TTOK*HDIM)
#define MAXROWS (TTOK*2)

#define BM 128
#define BN 64
#define BK 32
#define KP 36   // padded K stride in smem (36 mod 32 == 4 -> conflict-free frag loads)

// ---------------- scratch (static device globals; no runtime alloc) ----------------
__device__ int   g_cnt[NEXP];
__device__ int   g_off[NEXP];
__device__ int   g_cur[NEXP];
__device__ int   g_tok[MAXROWS];     // slot -> token id
__device__ float g_wt [MAXROWS];     // slot -> combine weight
__device__ int   g_tidx[TTOK*2];     // token -> its 2 expert ids
__device__ float g_tw  [TTOK*2];     // token -> its 2 normalized weights
__device__ float g_act[(size_t)MAXROWS*IDIM];  // 46MB: silu(g)*u per slot

// ---------------- helpers ----------------
__device__ __forceinline__ float tf32r(float f){
    unsigned u; asm("cvt.rna.tf32.f32 %0, %1;" : "=r"(u) : "f"(f));
    return __uint_as_float(u);
}

__device__ __forceinline__ void mma8(float* c, const unsigned* a, unsigned b0, unsigned b1){
    asm volatile(
      "mma.sync.aligned.m16n8k8.row.col.f32.tf32.tf32.f32 "
      "{%0,%1,%2,%3},{%4,%5,%6,%7},{%8,%9},{%0,%1,%2,%3};\n"
      : "+f"(c[0]),"+f"(c[1]),"+f"(c[2]),"+f"(c[3])
      : "r"(a[0]),"r"(a[1]),"r"(a[2]),"r"(a[3]),"r"(b0),"r"(b1));
}

// ---------------- kernel 0: zero final output region + counts ----------------
__global__ void k_zero(float4* __restrict__ out4){
    int i = blockIdx.x*blockDim.x + threadIdx.x;
    out4[i] = make_float4(0.f,0.f,0.f,0.f);
    if (i < NEXP) g_cnt[i] = 0;
}

// ---------------- kernel 1: router (one warp per token) ----------------
__global__ void k_router(const float* __restrict__ x, const float* __restrict__ gw,
                         float* __restrict__ logits_out){
    int warp = (blockIdx.x*blockDim.x + threadIdx.x) >> 5;
    int lane = threadIdx.x & 31;
    if (warp >= TTOK) return;
    const float* xr = x + (size_t)warp*HDIM;
    float acc[NEXP];
    #pragma unroll
    for (int e=0;e<NEXP;e++) acc[e]=0.f;
    for (int i=lane;i<HDIM;i+=32){
        float xv = xr[i];
        #pragma unroll
        for (int e=0;e<NEXP;e++) acc[e] += xv * __ldg(&gw[e*HDIM+i]);
    }
    #pragma unroll
    for (int e=0;e<NEXP;e++){
        float v = acc[e];
        #pragma unroll
        for (int o=16;o>0;o>>=1) v += __shfl_xor_sync(0xffffffffu, v, o);
        acc[e]=v;
    }
    if (lane==0){
        float m = acc[0];
        #pragma unroll
        for (int e=1;e<NEXP;e++) m = fmaxf(m, acc[e]);
        float p[NEXP];
        #pragma unroll
        for (int e=0;e<NEXP;e++){ p[e] = expf(acc[e]-m); logits_out[(size_t)warp*NEXP+e] = acc[e]; }
        int i1 = 0;
        #pragma unroll
        for (int e=1;e<NEXP;e++) if (p[e] > p[i1]) i1 = e;
        int i2 = (i1==0)?1:0;
        #pragma unroll
        for (int e=0;e<NEXP;e++) if (e!=i1 && p[e] > p[i2]) i2 = e;
        float w1=p[i1], w2=p[i2], inv = 1.f/(w1+w2);
        g_tidx[warp*2+0]=i1; g_tw[warp*2+0]=w1*inv;
        g_tidx[warp*2+1]=i2; g_tw[warp*2+1]=w2*inv;
        atomicAdd(&g_cnt[i1],1);
        atomicAdd(&g_cnt[i2],1);
    }
}

// ---------------- kernel 2: tiny exclusive scan ----------------
__global__ void k_scan(){
    if (threadIdx.x==0){
        int o=0;
        for (int e=0;e<NEXP;e++){ g_off[e]=o; g_cur[e]=o; o += g_cnt[e]; }
    }
}

// ---------------- kernel 3: compact placement ----------------
__global__ void k_place(){
    int t = blockIdx.x*blockDim.x + threadIdx.x;
    if (t >= TTOK) return;
    #pragma unroll
    for (int k=0;k<2;k++){
        int e = g_tidx[t*2+k];
        int pos = atomicAdd(&g_cur[e],1);
        g_tok[pos] = t;
        g_wt[pos]  = g_tw[t*2+k];
    }
}

// ---------------- kernel 4: grouped gate/up GEMM + SiLU ----------------
// C[Ne, I] for gate and up; A = gathered x rows, B = wg[e]/wu[e] ([I,H] row-major)
__global__ __launch_bounds__(256) void k_gate_up(
        const float* __restrict__ x,
        const float* __restrict__ wg, const float* __restrict__ wu){
    __shared__ float As[BM][KP];
    __shared__ float Bg[BN][KP];
    __shared__ float Bu[BN][KP];
    __shared__ int   stok[BM];

    int e   = blockIdx.z;
    int cnt = g_cnt[e];
    int m0  = blockIdx.x * BM;
    if (m0 >= cnt) return;
    int n0   = blockIdx.y * BN;
    int base = g_off[e];
    int tid  = threadIdx.x;

    if (tid < BM){
        int r = m0 + tid;
        stok[tid] = (r < cnt) ? g_tok[base + r] : g_tok[base];
    }
    __syncthreads();

    const float* wgp = wg + (size_t)e*IDIM*HDIM;
    const float* wup = wu + (size_t)e*IDIM*HDIM;

    float cg[2][4][4], cu[2][4][4];
    #pragma unroll
    for (int mi=0;mi<2;mi++)
        #pragma unroll
        for (int ni=0;ni<4;ni++)
            #pragma unroll
            for (int q=0;q<4;q++){ cg[mi][ni][q]=0.f; cu[mi][ni][q]=0.f; }

    int wid = tid>>5, lane = tid&31;
    int wm = (wid&3)*32, wn = (wid>>2)*32;
    int grp = lane>>2, thr = lane&3;

    float4 ra[4], rbg[2], rbu[2];

    // ---- load K-chunk 0 ----
    #pragma unroll
    for (int j=0;j<4;j++){
        int i = tid + j*256; int row = i>>3, k4 = i&7;
        ra[j] = *(const float4*)(&x[(size_t)stok[row]*HDIM + k4*4]);
    }
    #pragma unroll
    for (int j=0;j<2;j++){
        int i = tid + j*256; int n = i>>3, k4 = i&7;
        rbg[j] = *(const float4*)(&wgp[(size_t)(n0+n)*HDIM + k4*4]);
        rbu[j] = *(const float4*)(&wup[(size_t)(n0+n)*HDIM + k4*4]);
    }
    #pragma unroll
    for (int j=0;j<4;j++){
        int i = tid + j*256; int row = i>>3, k4 = i&7;
        As[row][k4*4+0]=tf32r(ra[j].x); As[row][k4*4+1]=tf32r(ra[j].y);
        As[row][k4*4+2]=tf32r(ra[j].z); As[row][k4*4+3]=tf32r(ra[j].w);
    }
    #pragma unroll
    for (int j=0;j<2;j++){
        int i = tid + j*256; int n = i>>3, k4 = i&7;
        Bg[n][k4*4+0]=tf32r(rbg[j].x); Bg[n][k4*4+1]=tf32r(rbg[j].y);
        Bg[n][k4*4+2]=tf32r(rbg[j].z); Bg[n][k4*4+3]=tf32r(rbg[j].w);
        Bu[n][k4*4+0]=tf32r(rbu[j].x); Bu[n][k4*4+1]=tf32r(rbu[j].y);
        Bu[n][k4*4+2]=tf32r(rbu[j].z); Bu[n][k4*4+3]=tf32r(rbu[j].w);
    }
    __syncthreads();

    for (int kk = BK; kk <= HDIM; kk += BK){
        bool more = (kk < HDIM);
        if (more){
            #pragma unroll
            for (int j=0;j<4;j++){
                int i = tid + j*256; int row = i>>3, k4 = i&7;
                ra[j] = *(const float4*)(&x[(size_t)stok[row]*HDIM + kk + k4*4]);
            }
            #pragma unroll
            for (int j=0;j<2;j++){
                int i = tid + j*256; int n = i>>3, k4 = i&7;
                rbg[j] = *(const float4*)(&wgp[(size_t)(n0+n)*HDIM + kk + k4*4]);
                rbu[j] = *(const float4*)(&wup[(size_t)(n0+n)*HDIM + kk + k4*4]);
            }
        }
        // ---- compute on current smem tile ----
        #pragma unroll
        for (int k8=0;k8<BK;k8+=8){
            unsigned a[2][4];
            #pragma unroll
            for (int mi=0;mi<2;mi++){
                int rb = wm + mi*16;
                a[mi][0] = __float_as_uint(As[rb+grp  ][k8+thr  ]);
                a[mi][1] = __float_as_uint(As[rb+8+grp][k8+thr  ]);
                a[mi][2] = __float_as_uint(As[rb+grp  ][k8+thr+4]);
                a[mi][3] = __float_as_uint(As[rb+8+grp][k8+thr+4]);
            }
            #pragma unroll
            for (int ni=0;ni<4;ni++){
                int nb = wn + ni*8 + grp;
                unsigned bg0 = __float_as_uint(Bg[nb][k8+thr  ]);
                unsigned bg1 = __float_as_uint(Bg[nb][k8+thr+4]);
                unsigned bu0 = __float_as_uint(Bu[nb][k8+thr  ]);
                unsigned bu1 = __float_as_uint(Bu[nb][k8+thr+4]);
                #pragma unroll
                for (int mi=0;mi<2;mi++){
                    mma8(cg[mi][ni], a[mi], bg0, bg1);
                    mma8(cu[mi][ni], a[mi], bu0, bu1);
                }
            }
        }
        __syncthreads();
        if (more){
            #pragma unroll
            for (int j=0;j<4;j++){
                int i = tid + j*256; int row = i>>3, k4 = i&7;
                As[row][k4*4+0]=tf32r(ra[j].x); As[row][k4*4+1]=tf32r(ra[j].y);
                As[row][k4*4+2]=tf32r(ra[j].z); As[row][k4*4+3]=tf32r(ra[j].w);
            }
            #pragma unroll
            for (int j=0;j<2;j++){
                int i = tid + j*256; int n = i>>3, k4 = i&7;
                Bg[n][k4*4+0]=tf32r(rbg[j].x); Bg[n][k4*4+1]=tf32r(rbg[j].y);
                Bg[n][k4*4+2]=tf32r(rbg[j].z); Bg[n][k4*4+3]=tf32r(rbg[j].w);
                Bu[n][k4*4+0]=tf32r(rbu[j].x); Bu[n][k4*4+1]=tf32r(rbu[j].y);
                Bu[n][k4*4+2]=tf32r(rbu[j].z); Bu[n][k4*4+3]=tf32r(rbu[j].w);
            }
            __syncthreads();
        }
    }

    // ---- epilogue: silu(g)*u -> g_act ----
    #pragma unroll
    for (int mi=0;mi<2;mi++){
        #pragma unroll
        for (int ni=0;ni<4;ni++){
            int ncol = n0 + wn + ni*8 + 2*thr;
            #pragma unroll
            for (int h=0;h<2;h++){
                int r = m0 + wm + mi*16 + grp + h*8;
                if (r < cnt){
                    size_t ro = (size_t)(base + r)*IDIM;
                    float g0 = cg[mi][ni][h*2+0], g1 = cg[mi][ni][h*2+1];
                    float u0 = cu[mi][ni][h*2+0], u1 = cu[mi][ni][h*2+1];
                    g_act[ro + ncol  ] = g0/(1.f+expf(-g0))*u0;
                    g_act[ro + ncol+1] = g1/(1.f+expf(-g1))*u1;
                }
            }
        }
    }
}

// ---------------- kernel 5: grouped down GEMM + weighted scatter ----------------
__global__ __launch_bounds__(256) void k_down(
        const float* __restrict__ wd, float* __restrict__ out){
    __shared__ float As[BM][KP];
    __shared__ float Bs[BN][KP];
    __shared__ int   stok[BM];
    __shared__ float swt[BM];

    int e   = blockIdx.z;
    int cnt = g_cnt[e];
    int m0  = blockIdx.x * BM;
    if (m0 >= cnt) return;
    int n0   = blockIdx.y * BN;
    int base = g_off[e];
    int tid  = threadIdx.x;

    if (tid < BM){
        int r = m0 + tid;
        bool v = (r < cnt);
        stok[tid] = v ? g_tok[base + r] : 0;
        swt[tid]  = v ? g_wt[base + r] : 0.f;
    }
    __syncthreads();

    const float* wdp = wd + (size_t)e*HDIM*IDIM;

    float cc[2][4][4];
    #pragma unroll
    for (int mi=0;mi<2;mi++)
        #pragma unroll
        for (int ni=0;ni<4;ni++)
            #pragma unroll
            for (int q=0;q<4;q++) cc[mi][ni][q]=0.f;

    int wid = tid>>5, lane = tid&31;
    int wm = (wid&3)*32, wn = (wid>>2)*32;
    int grp = lane>>2, thr = lane&3;

    float4 ra[4], rb[2];

    // load K-chunk 0
    #pragma unroll
    for (int j=0;j<4;j++){
        int i = tid + j*256; int row = i>>3, k4 = i&7;
        int rr = m0 + row; if (rr >= cnt) rr = m0;
        ra[j] = *(const float4*)(&g_act[(size_t)(base+rr)*IDIM + k4*4]);
    }
    #pragma unroll
    for (int j=0;j<2;j++){
        int i = tid + j*256; int n = i>>3, k4 = i&7;
        rb[j] = *(const float4*)(&wdp[(size_t)(n0+n)*IDIM + k4*4]);
    }
    #pragma unroll
    for (int j=0;j<4;j++){
        int i = tid + j*256; int row = i>>3, k4 = i&7;
        As[row][k4*4+0]=tf32r(ra[j].x); As[row][k4*4+1]=tf32r(ra[j].y);
        As[row][k4*4+2]=tf32r(ra[j].z); As[row][k4*4+3]=tf32r(ra[j].w);
    }
    #pragma unroll
    for (int j=0;j<2;j++){
        int i = tid + j*256; int n = i>>3, k4 = i&7;
        Bs[n][k4*4+0]=tf32r(rb[j].x); Bs[n][k4*4+1]=tf32r(rb[j].y);
        Bs[n][k4*4+2]=tf32r(rb[j].z); Bs[n][k4*4+3]=tf32r(rb[j].w);
    }
    __syncthreads();

    for (int kk = BK; kk <= IDIM; kk += BK){
        bool more = (kk < IDIM);
        if (more){
            #pragma unroll
            for (int j=0;j<4;j++){
                int i = tid + j*256; int row = i>>3, k4 = i&7;
                int rr = m0 + row; if (rr >= cnt) rr = m0;
                ra[j] = *(const float4*)(&g_act[(size_t)(base+rr)*IDIM + kk + k4*4]);
            }
            #pragma unroll
            for (int j=0;j<2;j++){
                int i = tid + j*256; int n = i>>3, k4 = i&7;
                rb[j] = *(const float4*)(&wdp[(size_t)(n0+n)*IDIM + kk + k4*4]);
            }
        }
        #pragma unroll
        for (int k8=0;k8<BK;k8+=8){
            unsigned a[2][4];
            #pragma unroll
            for (int mi=0;mi<2;mi++){
                int rbse = wm + mi*16;
                a[mi][0] = __float_as_uint(As[rbse+grp  ][k8+thr  ]);
                a[mi][1] = __float_as_uint(As[rbse+8+grp][k8+thr  ]);
                a[mi][2] = __float_as_uint(As[rbse+grp  ][k8+thr+4]);
                a[mi][3] = __float_as_uint(As[rbse+8+grp][k8+thr+4]);
            }
            #pragma unroll
            for (int ni=0;ni<4;ni++){
                int nb = wn + ni*8 + grp;
                unsigned b0 = __float_as_uint(Bs[nb][k8+thr  ]);
                unsigned b1 = __float_as_uint(Bs[nb][k8+thr+4]);
                #pragma unroll
                for (int mi=0;mi<2;mi++) mma8(cc[mi][ni], a[mi], b0, b1);
            }
        }
        __syncthreads();
        if (more){
            #pragma unroll
            for (int j=0;j<4;j++){
                int i = tid + j*256; int row = i>>3, k4 = i&7;
                As[row][k4*4+0]=tf32r(ra[j].x); As[row][k4*4+1]=tf32r(ra[j].y);
                As[row][k4*4+2]=tf32r(ra[j].z); As[row][k4*4+3]=tf32r(ra[j].w);
            }
            #pragma unroll
            for (int j=0;j<2;j++){
                int i = tid + j*256; int n = i>>3, k4 = i&7;
                Bs[n][k4*4+0]=tf32r(rb[j].x); Bs[n][k4*4+1]=tf32r(rb[j].y);
                Bs[n][k4*4+2]=tf32r(rb[j].z); Bs[n][k4*4+3]=tf32r(rb[j].w);
            }
            __syncthreads();
        }
    }

    // epilogue: weighted atomic scatter
    #pragma unroll
    for (int mi=0;mi<2;mi++){
        #pragma unroll
        for (int ni=0;ni<4;ni++){
            int ncol = n0 + wn + ni*8 + 2*thr;
            #pragma unroll
            for (int h=0;h<2;h++){
                int rloc = wm + mi*16 + grp + h*8;
                int r = m0 + rloc;
                if (r < cnt){
                    float w = swt[rloc];
                    size_t o = (size_t)stok[rloc]*HDIM + ncol;
                    atomicAdd(&out[o  ], cc[mi][ni][h*2+0]*w);
                    atomicAdd(&out[o+1], cc[mi][ni][h*2+1]*w);
                }
            }
        }
    }
}

// ---------------- launch ----------------
extern "C" void kernel_launch(void* const* d_in, const int* in_sizes, int n_in,
                              void* d_out, int out_size){
    const float* x  = (const float*)d_in[0];   // [2,2048,H]
    const float* gw = (const float*)d_in[1];   // [E,H]
    const float* wg = (const float*)d_in[2];   // [E,I,H]
    const float* wu = (const float*)d_in[3];   // [E,I,H]
    const float* wd = (const float*)d_in[4];   // [E,H,I]
    float* out = (float*)d_out;                // final [T,H] then router_logits [T,E]

    k_zero<<<FINAL_ELEMS/4/256, 256>>>((float4*)out);
    k_router<<<TTOK/4, 128>>>(x, gw, out + FINAL_ELEMS);
    k_scan<<<1, 32>>>();
    k_place<<<TTOK/256, 256>>>();
    dim3 g1(TTOK/BM, IDIM/BN, NEXP);   // (32, 22, 8)
    k_gate_up<<<g1, 256>>>(x, wg, wu);
    dim3 g2(TTOK/BM, HDIM/BN, NEXP);   // (32, 32, 8)
    k_down<<<g2, 256>>>(wd, out);
}